// round 3
// baseline (speedup 1.0000x reference)
#include <cuda_runtime.h>
#include <math.h>

#define BB   2
#define SS   2048
#define DD   512
#define HH   8
#define DHH  64
#define DFFN 2048
#define MTOK (BB*SS)      // 4096 token rows
#define EPSV 1e-5f

// ---------------- scratch (static device globals; no allocation) -------------
__device__ float g_q  [MTOK*DD];
__device__ float g_k  [MTOK*DD];
__device__ float g_v  [MTOK*DD];
__device__ float g_ctx[MTOK*DD];
__device__ float g_ao [MTOK*DD];
__device__ float g_h  [MTOK*DD];
__device__ float g_ff1[MTOK*DFFN];
__device__ float g_ff2[MTOK*DD];

// ---------------- generic SGEMM: C[M,N] = A[M,K] @ B[N,K]^T + bias ----------
// EPI: 0 = bias, 1 = bias + ReLU
// BM=BN=64, BK=16, 256 threads, 4x4 per-thread microtile.
template<int EPI>
__global__ __launch_bounds__(256)
void sgemm_nt(const float* __restrict__ A, const float* __restrict__ Bw,
              const float* __restrict__ bias, float* __restrict__ C,
              int M, int N, int K)
{
    __shared__ float As[16][64];
    __shared__ float Bs[16][64];

    const int t  = threadIdx.x;
    const int tx = t & 15;
    const int ty = t >> 4;
    const int bm = blockIdx.y * 64;
    const int bn = blockIdx.x * 64;

    const int lr = t >> 2;          // 0..63 : tile row (A) / tile col-row (B)
    const int lk = (t & 3) << 2;    // 0,4,8,12 : k offset

    const float* Ag = A  + (size_t)(bm + lr) * K + lk;
    const float* Bg = Bw + (size_t)(bn + lr) * K + lk;

    float acc[4][4] = {};

    for (int kt = 0; kt < K; kt += 16) {
        float4 a4 = *(const float4*)(Ag + kt);
        float4 b4 = *(const float4*)(Bg + kt);
        As[lk+0][lr] = a4.x; As[lk+1][lr] = a4.y;
        As[lk+2][lr] = a4.z; As[lk+3][lr] = a4.w;
        Bs[lk+0][lr] = b4.x; Bs[lk+1][lr] = b4.y;
        Bs[lk+2][lr] = b4.z; Bs[lk+3][lr] = b4.w;
        __syncthreads();

#pragma unroll
        for (int kk = 0; kk < 16; kk++) {
            float4 av = *(const float4*)&As[kk][ty*4];
            float4 bv = *(const float4*)&Bs[kk][tx*4];
            float a[4] = {av.x, av.y, av.z, av.w};
            float b[4] = {bv.x, bv.y, bv.z, bv.w};
#pragma unroll
            for (int i = 0; i < 4; i++)
#pragma unroll
                for (int j = 0; j < 4; j++)
                    acc[i][j] += a[i] * b[j];
        }
        __syncthreads();
    }

    const int cn = bn + tx*4;
    float b0 = bias[cn+0], b1 = bias[cn+1], b2 = bias[cn+2], b3 = bias[cn+3];
#pragma unroll
    for (int i = 0; i < 4; i++) {
        int row = bm + ty*4 + i;
        float4 o;
        o.x = acc[i][0] + b0;
        o.y = acc[i][1] + b1;
        o.z = acc[i][2] + b2;
        o.w = acc[i][3] + b3;
        if (EPI == 1) {
            o.x = fmaxf(o.x, 0.f); o.y = fmaxf(o.y, 0.f);
            o.z = fmaxf(o.z, 0.f); o.w = fmaxf(o.w, 0.f);
        }
        *(float4*)(C + (size_t)row * N + cn) = o;
    }
}

// ---------------- flash attention (causal), fp32 ----------------------------
// q/k/v/ctx live token-major [B,S,D]; head h occupies columns [h*64, h*64+64).
// One thread owns one query row; 128 query rows / block; K/V tiles of 64 keys
// staged in SMEM (broadcast LDS.128 reads -> 4 FMA per LDS).
__global__ __launch_bounds__(128)
void flash_kernel(const float* __restrict__ alphas)
{
    __shared__ float sm[128 * 64];      // 32 KB, reused: Q stage then K|V tiles

    const int tid = threadIdx.x;
    const int qb  = blockIdx.x;
    const int bh  = blockIdx.y;
    const int b   = bh / HH;
    const int h   = bh % HH;
    const int q0  = qb * 128;

    const float* qbase = g_q + (size_t)b * SS * DD + h * DHH;
    const float* kbase = g_k + (size_t)b * SS * DD + h * DHH;
    const float* vbase = g_v + (size_t)b * SS * DD + h * DHH;

    // stage Q tile coalesced, then pull own row into registers
    for (int i = tid; i < 128 * 16; i += 128) {
        int r = i >> 4, c4 = i & 15;
        ((float4*)sm)[r * 16 + c4] =
            *(const float4*)(qbase + (size_t)(q0 + r) * DD + c4 * 4);
    }
    __syncthreads();

    float q[64];
#pragma unroll
    for (int d4 = 0; d4 < 16; d4++) {
        float4 v4 = ((float4*)sm)[tid * 16 + d4];
        q[d4*4+0] = v4.x; q[d4*4+1] = v4.y; q[d4*4+2] = v4.z; q[d4*4+3] = v4.w;
    }
    __syncthreads();

    float ctx[64];
#pragma unroll
    for (int d = 0; d < 64; d++) ctx[d] = 0.f;
    float m = -1e30f, l = 0.f;

    const int row    = q0 + tid;
    const int ntiles = qb * 2 + 2;          // causal: keys up to q0+127

    float* Ks = sm;                 // [64][64]
    float* Vs = sm + 64 * 64;       // [64][64]

    for (int jt = 0; jt < ntiles; jt++) {
        const int k0 = jt * 64;
        for (int i = tid; i < 64 * 16; i += 128) {
            int r = i >> 4, c4 = i & 15;
            ((float4*)Ks)[r*16+c4] = *(const float4*)(kbase + (size_t)(k0+r)*DD + c4*4);
            ((float4*)Vs)[r*16+c4] = *(const float4*)(vbase + (size_t)(k0+r)*DD + c4*4);
        }
        __syncthreads();

        const bool need_mask = (jt >= qb * 2);   // only the 2 diagonal tiles

        for (int ch = 0; ch < 2; ch++) {
            float s[32];
#pragma unroll
            for (int jj = 0; jj < 32; jj++) {
                const int j = ch * 32 + jj;
                const float4* kr = (const float4*)(Ks + j * 64);
                float acc = 0.f;
#pragma unroll
                for (int d4 = 0; d4 < 16; d4++) {
                    float4 kv = kr[d4];
                    acc += q[d4*4+0]*kv.x + q[d4*4+1]*kv.y
                         + q[d4*4+2]*kv.z + q[d4*4+3]*kv.w;
                }
                s[jj] = acc * 0.125f;                       // 1/sqrt(64)
                if (need_mask && (k0 + j > row)) s[jj] = -1e30f;
            }

            float mc = s[0];
#pragma unroll
            for (int jj = 1; jj < 32; jj++) mc = fmaxf(mc, s[jj]);
            const float mn   = fmaxf(m, mc);
            const float corr = __expf(m - mn);
            l *= corr;
#pragma unroll
            for (int d = 0; d < 64; d++) ctx[d] *= corr;

#pragma unroll
            for (int jj = 0; jj < 32; jj++) {
                const float p = __expf(s[jj] - mn);
                l += p;
                const float4* vr = (const float4*)(Vs + (ch*32 + jj) * 64);
#pragma unroll
                for (int d4 = 0; d4 < 16; d4++) {
                    float4 vv = vr[d4];
                    ctx[d4*4+0] += p * vv.x;
                    ctx[d4*4+1] += p * vv.y;
                    ctx[d4*4+2] += p * vv.z;
                    ctx[d4*4+3] += p * vv.w;
                }
            }
            m = mn;
        }
        __syncthreads();
    }

    const float sc = alphas[h] / l;
    float* op = g_ctx + (size_t)b * SS * DD + (size_t)row * DD + h * DHH;
#pragma unroll
    for (int d4 = 0; d4 < 16; d4++) {
        ((float4*)op)[d4] = make_float4(ctx[d4*4+0]*sc, ctx[d4*4+1]*sc,
                                        ctx[d4*4+2]*sc, ctx[d4*4+3]*sc);
    }
}

// ---------------- fused residual add + LayerNorm -----------------------------
// out[row] = LN(A[row] + B[row]) * g + be ; one block (128 thr) per 512-row
__global__ __launch_bounds__(128)
void add_ln_kernel(const float* __restrict__ A, const float* __restrict__ Bv,
                   const float* __restrict__ g, const float* __restrict__ be,
                   float* __restrict__ out)
{
    __shared__ float sh_s[4], sh_s2[4];
    const int row = blockIdx.x;
    const int t   = threadIdx.x;

    float4 a4 = ((const float4*)(A  + (size_t)row * DD))[t];
    float4 b4 = ((const float4*)(Bv + (size_t)row * DD))[t];
    float v0 = a4.x + b4.x, v1 = a4.y + b4.y, v2 = a4.z + b4.z, v3 = a4.w + b4.w;

    float s  = v0 + v1 + v2 + v3;
    float s2 = v0*v0 + v1*v1 + v2*v2 + v3*v3;
#pragma unroll
    for (int o = 16; o; o >>= 1) {
        s  += __shfl_xor_sync(0xffffffffu, s,  o);
        s2 += __shfl_xor_sync(0xffffffffu, s2, o);
    }
    const int w = t >> 5;
    if ((t & 31) == 0) { sh_s[w] = s; sh_s2[w] = s2; }
    __syncthreads();
    s  = sh_s[0] + sh_s[1] + sh_s[2] + sh_s[3];
    s2 = sh_s2[0] + sh_s2[1] + sh_s2[2] + sh_s2[3];

    const float mu  = s  * (1.0f / DD);
    const float var = s2 * (1.0f / DD) - mu * mu;
    const float r   = rsqrtf(var + EPSV);

    float4 g4 = ((const float4*)g)[t];
    float4 e4 = ((const float4*)be)[t];
    float4 o;
    o.x = (v0 - mu) * r * g4.x + e4.x;
    o.y = (v1 - mu) * r * g4.y + e4.y;
    o.z = (v2 - mu) * r * g4.z + e4.z;
    o.w = (v3 - mu) * r * g4.w + e4.w;
    ((float4*)(out + (size_t)row * DD))[t] = o;
}

// ---------------- launch ------------------------------------------------------
extern "C" void kernel_launch(void* const* d_in, const int* in_sizes, int n_in,
                              void* d_out, int out_size)
{
    const float* x     = (const float*)d_in[0];
    // d_in[1] = attn_mask: exact causal mask; implemented analytically.
    const float* Wq    = (const float*)d_in[2];
    const float* bq    = (const float*)d_in[3];
    const float* Wk    = (const float*)d_in[4];
    const float* bk    = (const float*)d_in[5];
    const float* Wv    = (const float*)d_in[6];
    const float* bv    = (const float*)d_in[7];
    const float* Wo    = (const float*)d_in[8];
    const float* bo    = (const float*)d_in[9];
    const float* alph  = (const float*)d_in[10];
    const float* ln1g  = (const float*)d_in[11];
    const float* ln1b  = (const float*)d_in[12];
    const float* W1    = (const float*)d_in[13];
    const float* b1    = (const float*)d_in[14];
    const float* W2    = (const float*)d_in[15];
    const float* b2    = (const float*)d_in[16];
    const float* ln2g  = (const float*)d_in[17];
    const float* ln2b  = (const float*)d_in[18];

    float *qb, *kb, *vb, *ctxb, *aob, *hb, *ff1, *ff2;
    cudaGetSymbolAddress((void**)&qb,   g_q);
    cudaGetSymbolAddress((void**)&kb,   g_k);
    cudaGetSymbolAddress((void**)&vb,   g_v);
    cudaGetSymbolAddress((void**)&ctxb, g_ctx);
    cudaGetSymbolAddress((void**)&aob,  g_ao);
    cudaGetSymbolAddress((void**)&hb,   g_h);
    cudaGetSymbolAddress((void**)&ff1,  g_ff1);
    cudaGetSymbolAddress((void**)&ff2,  g_ff2);

    const dim3 gProj(DD / 64, MTOK / 64);     // (8, 64)
    const dim3 gFF1 (DFFN / 64, MTOK / 64);   // (32, 64)

    // QKV projections
    sgemm_nt<0><<<gProj, 256>>>(x, Wq, bq, qb, MTOK, DD, DD);
    sgemm_nt<0><<<gProj, 256>>>(x, Wk, bk, kb, MTOK, DD, DD);
    sgemm_nt<0><<<gProj, 256>>>(x, Wv, bv, vb, MTOK, DD, DD);

    // causal flash attention + head_alphas
    flash_kernel<<<dim3(SS / 128, BB * HH), 128>>>(alph);

    // output projection, residual + LN1
    sgemm_nt<0><<<gProj, 256>>>(ctxb, Wo, bo, aob, MTOK, DD, DD);
    add_ln_kernel<<<MTOK, 128>>>(x, aob, ln1g, ln1b, hb);

    // FFN
    sgemm_nt<1><<<gFF1, 256>>>(hb, W1, b1, ff1, MTOK, DFFN, DD);
    sgemm_nt<0><<<gProj, 256>>>(ff1, W2, b2, ff2, MTOK, DD, DFFN);

    // residual + LN2 -> output
    add_ln_kernel<<<MTOK, 128>>>(hb, ff2, ln2g, ln2b, (float*)d_out);
}

// round 5
// speedup vs baseline: 1.2252x; 1.2252x over previous
#include <cuda_runtime.h>
#include <math.h>

#define BB   2
#define SS   2048
#define DD   512
#define HH   8
#define DHH  64
#define DFFN 2048
#define MTOK (BB*SS)      // 4096 token rows
#define EPSV 1e-5f

// ---------------- scratch (static device globals; no allocation) -------------
__device__ float g_q  [MTOK*DD];
__device__ float g_k  [MTOK*DD];
__device__ float g_v  [MTOK*DD];
__device__ float g_ctx[MTOK*DD];
__device__ float g_ao [MTOK*DD];
__device__ float g_h  [MTOK*DD];
__device__ float g_ff1[MTOK*DFFN];
__device__ float g_ff2[MTOK*DD];

// ---------------- SGEMM: C[M,N] = A[M,K] @ B[N,K]^T + bias ------------------
// EPI: 0 = bias, 1 = bias + ReLU
// BM=BN=128, BK=16, 256 threads, 8x8 microtile (split 4+4), reg prefetch.
template<int EPI>
__global__ __launch_bounds__(256, 2)
void sgemm_nt(const float* __restrict__ A, const float* __restrict__ Bw,
              const float* __restrict__ bias, float* __restrict__ C,
              int M, int N, int K)
{
    __shared__ float As[16][128];
    __shared__ float Bs[16][128];

    const int t  = threadIdx.x;
    const int tx = t & 15;          // 16 col groups
    const int ty = t >> 4;          // 16 row groups
    const int bm = blockIdx.y * 128;
    const int bn = blockIdx.x * 128;

    const int lr = t >> 2;          // 0..63
    const int lk = (t & 3) << 2;    // 0,4,8,12

    const float* Ag0 = A  + (size_t)(bm + lr)      * K + lk;
    const float* Ag1 = A  + (size_t)(bm + 64 + lr) * K + lk;
    const float* Bg0 = Bw + (size_t)(bn + lr)      * K + lk;
    const float* Bg1 = Bw + (size_t)(bn + 64 + lr) * K + lk;

    // prefetch first k-tile into registers
    float4 pa0 = *(const float4*)(Ag0);
    float4 pa1 = *(const float4*)(Ag1);
    float4 pb0 = *(const float4*)(Bg0);
    float4 pb1 = *(const float4*)(Bg1);

    float acc[8][8] = {};

    for (int kt = 0; kt < K; kt += 16) {
        // commit prefetched tile to smem (transposed: [k][m])
        As[lk+0][lr]    = pa0.x; As[lk+1][lr]    = pa0.y;
        As[lk+2][lr]    = pa0.z; As[lk+3][lr]    = pa0.w;
        As[lk+0][64+lr] = pa1.x; As[lk+1][64+lr] = pa1.y;
        As[lk+2][64+lr] = pa1.z; As[lk+3][64+lr] = pa1.w;
        Bs[lk+0][lr]    = pb0.x; Bs[lk+1][lr]    = pb0.y;
        Bs[lk+2][lr]    = pb0.z; Bs[lk+3][lr]    = pb0.w;
        Bs[lk+0][64+lr] = pb1.x; Bs[lk+1][64+lr] = pb1.y;
        Bs[lk+2][64+lr] = pb1.z; Bs[lk+3][64+lr] = pb1.w;
        __syncthreads();

        // issue next tile's global loads early (hidden under FFMA phase)
        if (kt + 16 < K) {
            pa0 = *(const float4*)(Ag0 + kt + 16);
            pa1 = *(const float4*)(Ag1 + kt + 16);
            pb0 = *(const float4*)(Bg0 + kt + 16);
            pb1 = *(const float4*)(Bg1 + kt + 16);
        }

#pragma unroll
        for (int kk = 0; kk < 16; kk++) {
            float4 a0 = *(const float4*)&As[kk][ty*4];
            float4 a1 = *(const float4*)&As[kk][64 + ty*4];
            float4 b0 = *(const float4*)&Bs[kk][tx*4];
            float4 b1 = *(const float4*)&Bs[kk][64 + tx*4];
            float a[8] = {a0.x,a0.y,a0.z,a0.w, a1.x,a1.y,a1.z,a1.w};
            float b[8] = {b0.x,b0.y,b0.z,b0.w, b1.x,b1.y,b1.z,b1.w};
#pragma unroll
            for (int i = 0; i < 8; i++)
#pragma unroll
                for (int j = 0; j < 8; j++)
                    acc[i][j] += a[i] * b[j];
        }
        __syncthreads();
    }

    // epilogue: rows r = bm + g*64 + ty*4 + i ; cols c = bn + cg*64 + tx*4 + j
    float4 bb0 = *(const float4*)(bias + bn + tx*4);
    float4 bb1 = *(const float4*)(bias + bn + 64 + tx*4);
#pragma unroll
    for (int g = 0; g < 2; g++) {
#pragma unroll
        for (int i = 0; i < 4; i++) {
            const int row = bm + g*64 + ty*4 + i;
            float* crow = C + (size_t)row * N + bn;
            float4 o0, o1;
            o0.x = acc[g*4+i][0] + bb0.x; o0.y = acc[g*4+i][1] + bb0.y;
            o0.z = acc[g*4+i][2] + bb0.z; o0.w = acc[g*4+i][3] + bb0.w;
            o1.x = acc[g*4+i][4] + bb1.x; o1.y = acc[g*4+i][5] + bb1.y;
            o1.z = acc[g*4+i][6] + bb1.z; o1.w = acc[g*4+i][7] + bb1.w;
            if (EPI == 1) {
                o0.x = fmaxf(o0.x, 0.f); o0.y = fmaxf(o0.y, 0.f);
                o0.z = fmaxf(o0.z, 0.f); o0.w = fmaxf(o0.w, 0.f);
                o1.x = fmaxf(o1.x, 0.f); o1.y = fmaxf(o1.y, 0.f);
                o1.z = fmaxf(o1.z, 0.f); o1.w = fmaxf(o1.w, 0.f);
            }
            *(float4*)(crow + tx*4)      = o0;
            *(float4*)(crow + 64 + tx*4) = o1;
        }
    }
}

// ---------------- flash attention (causal), fp32 ----------------------------
// Two threads per query row (32 dims each); 64 query rows per block; score
// chunks of 16 keys; K/V tiles of 64 keys staged in SMEM. Register footprint
// halved vs one-thread-per-row -> much higher occupancy.
__global__ __launch_bounds__(128, 3)
void flash_kernel(const float* __restrict__ alphas)
{
    __shared__ float Ks[64 * 64];
    __shared__ float Vs[64 * 64];

    const int tid  = threadIdx.x;
    const int rloc = tid >> 1;          // 0..63 query row in block
    const int half = tid & 1;           // which 32-dim half of the head
    const int qb   = blockIdx.x;        // 0..31
    const int bh   = blockIdx.y;
    const int b    = bh / HH;
    const int h    = bh % HH;
    const int q0   = qb * 64;
    const int row  = q0 + rloc;

    const float* qbase = g_q + (size_t)b * SS * DD + h * DHH;
    const float* kbase = g_k + (size_t)b * SS * DD + h * DHH;
    const float* vbase = g_v + (size_t)b * SS * DD + h * DHH;

    // own half of the query row straight from gmem
    float q[32];
    {
        const float4* qp = (const float4*)(qbase + (size_t)row * DD + half * 32);
#pragma unroll
        for (int d4 = 0; d4 < 8; d4++) {
            float4 v4 = qp[d4];
            q[d4*4+0] = v4.x; q[d4*4+1] = v4.y;
            q[d4*4+2] = v4.z; q[d4*4+3] = v4.w;
        }
    }

    float ctx[32];
#pragma unroll
    for (int d = 0; d < 32; d++) ctx[d] = 0.f;
    float m = -1e30f, l = 0.f;

    const int ntiles = qb + 1;          // causal: keys up to q0+63

    for (int jt = 0; jt < ntiles; jt++) {
        const int k0 = jt * 64;
        // stage K,V tiles coalesced: 64 rows x 64 dims each
        for (int i = tid; i < 64 * 16; i += 128) {
            int r = i >> 4, c4 = i & 15;
            ((float4*)Ks)[r*16+c4] = *(const float4*)(kbase + (size_t)(k0+r)*DD + c4*4);
            ((float4*)Vs)[r*16+c4] = *(const float4*)(vbase + (size_t)(k0+r)*DD + c4*4);
        }
        __syncthreads();

        const bool need_mask = (jt == qb);     // only the diagonal tile

#pragma unroll 1
        for (int ch = 0; ch < 4; ch++) {       // 4 chunks of 16 keys
            float s[16];
#pragma unroll
            for (int jj = 0; jj < 16; jj++) {
                const int j = ch * 16 + jj;
                const float4* kr = (const float4*)(Ks + j * 64 + half * 32);
                float acc = 0.f;
#pragma unroll
                for (int d4 = 0; d4 < 8; d4++) {
                    float4 kv = kr[d4];
                    acc += q[d4*4+0]*kv.x + q[d4*4+1]*kv.y
                         + q[d4*4+2]*kv.z + q[d4*4+3]*kv.w;
                }
                // combine the two 32-dim partials of this row
                acc += __shfl_xor_sync(0xffffffffu, acc, 1);
                s[jj] = acc * 0.125f;                       // 1/sqrt(64)
                if (need_mask && (k0 + j > row)) s[jj] = -1e30f;
            }

            float mc = s[0];
#pragma unroll
            for (int jj = 1; jj < 16; jj++) mc = fmaxf(mc, s[jj]);
            const float mn   = fmaxf(m, mc);
            const float corr = __expf(m - mn);
            l *= corr;
#pragma unroll
            for (int d = 0; d < 32; d++) ctx[d] *= corr;

#pragma unroll
            for (int jj = 0; jj < 16; jj++) {
                const float p = __expf(s[jj] - mn);
                l += p;
                const float4* vr = (const float4*)(Vs + (ch*16 + jj) * 64 + half * 32);
#pragma unroll
                for (int d4 = 0; d4 < 8; d4++) {
                    float4 vv = vr[d4];
                    ctx[d4*4+0] += p * vv.x;
                    ctx[d4*4+1] += p * vv.y;
                    ctx[d4*4+2] += p * vv.z;
                    ctx[d4*4+3] += p * vv.w;
                }
            }
            m = mn;
        }
        __syncthreads();
    }

    const float sc = alphas[h] / l;
    float* op = g_ctx + (size_t)b * SS * DD + (size_t)row * DD + h * DHH + half * 32;
#pragma unroll
    for (int d4 = 0; d4 < 8; d4++) {
        ((float4*)op)[d4] = make_float4(ctx[d4*4+0]*sc, ctx[d4*4+1]*sc,
                                        ctx[d4*4+2]*sc, ctx[d4*4+3]*sc);
    }
}

// ---------------- fused residual add + LayerNorm -----------------------------
__global__ __launch_bounds__(128)
void add_ln_kernel(const float* __restrict__ A, const float* __restrict__ Bv,
                   const float* __restrict__ g, const float* __restrict__ be,
                   float* __restrict__ out)
{
    __shared__ float sh_s[4], sh_s2[4];
    const int row = blockIdx.x;
    const int t   = threadIdx.x;

    float4 a4 = ((const float4*)(A  + (size_t)row * DD))[t];
    float4 b4 = ((const float4*)(Bv + (size_t)row * DD))[t];
    float v0 = a4.x + b4.x, v1 = a4.y + b4.y, v2 = a4.z + b4.z, v3 = a4.w + b4.w;

    float s  = v0 + v1 + v2 + v3;
    float s2 = v0*v0 + v1*v1 + v2*v2 + v3*v3;
#pragma unroll
    for (int o = 16; o; o >>= 1) {
        s  += __shfl_xor_sync(0xffffffffu, s,  o);
        s2 += __shfl_xor_sync(0xffffffffu, s2, o);
    }
    const int w = t >> 5;
    if ((t & 31) == 0) { sh_s[w] = s; sh_s2[w] = s2; }
    __syncthreads();
    s  = sh_s[0] + sh_s[1] + sh_s[2] + sh_s[3];
    s2 = sh_s2[0] + sh_s2[1] + sh_s2[2] + sh_s2[3];

    const float mu  = s  * (1.0f / DD);
    const float var = s2 * (1.0f / DD) - mu * mu;
    const float r   = rsqrtf(var + EPSV);

    float4 g4 = ((const float4*)g)[t];
    float4 e4 = ((const float4*)be)[t];
    float4 o;
    o.x = (v0 - mu) * r * g4.x + e4.x;
    o.y = (v1 - mu) * r * g4.y + e4.y;
    o.z = (v2 - mu) * r * g4.z + e4.z;
    o.w = (v3 - mu) * r * g4.w + e4.w;
    ((float4*)(out + (size_t)row * DD))[t] = o;
}

// ---------------- launch ------------------------------------------------------
extern "C" void kernel_launch(void* const* d_in, const int* in_sizes, int n_in,
                              void* d_out, int out_size)
{
    const float* x     = (const float*)d_in[0];
    // d_in[1] = attn_mask: exact causal mask; implemented analytically.
    const float* Wq    = (const float*)d_in[2];
    const float* bq    = (const float*)d_in[3];
    const float* Wk    = (const float*)d_in[4];
    const float* bk    = (const float*)d_in[5];
    const float* Wv    = (const float*)d_in[6];
    const float* bv    = (const float*)d_in[7];
    const float* Wo    = (const float*)d_in[8];
    const float* bo    = (const float*)d_in[9];
    const float* alph  = (const float*)d_in[10];
    const float* ln1g  = (const float*)d_in[11];
    const float* ln1b  = (const float*)d_in[12];
    const float* W1    = (const float*)d_in[13];
    const float* b1    = (const float*)d_in[14];
    const float* W2    = (const float*)d_in[15];
    const float* b2    = (const float*)d_in[16];
    const float* ln2g  = (const float*)d_in[17];
    const float* ln2b  = (const float*)d_in[18];

    float *qb, *kb, *vb, *ctxb, *aob, *hb, *ff1, *ff2;
    cudaGetSymbolAddress((void**)&qb,   g_q);
    cudaGetSymbolAddress((void**)&kb,   g_k);
    cudaGetSymbolAddress((void**)&vb,   g_v);
    cudaGetSymbolAddress((void**)&ctxb, g_ctx);
    cudaGetSymbolAddress((void**)&aob,  g_ao);
    cudaGetSymbolAddress((void**)&hb,   g_h);
    cudaGetSymbolAddress((void**)&ff1,  g_ff1);
    cudaGetSymbolAddress((void**)&ff2,  g_ff2);

    const dim3 gProj(DD / 128, MTOK / 128);     // (4, 32)
    const dim3 gFF1 (DFFN / 128, MTOK / 128);   // (16, 32)

    // QKV projections
    sgemm_nt<0><<<gProj, 256>>>(x, Wq, bq, qb, MTOK, DD, DD);
    sgemm_nt<0><<<gProj, 256>>>(x, Wk, bk, kb, MTOK, DD, DD);
    sgemm_nt<0><<<gProj, 256>>>(x, Wv, bv, vb, MTOK, DD, DD);

    // causal flash attention + head_alphas
    flash_kernel<<<dim3(SS / 64, BB * HH), 128>>>(alph);

    // output projection, residual + LN1
    sgemm_nt<0><<<gProj, 256>>>(ctxb, Wo, bo, aob, MTOK, DD, DD);
    add_ln_kernel<<<MTOK, 128>>>(x, aob, ln1g, ln1b, hb);

    // FFN
    sgemm_nt<1><<<gFF1, 256>>>(hb, W1, b1, ff1, MTOK, DFFN, DD);
    sgemm_nt<0><<<gProj, 256>>>(ff1, W2, b2, ff2, MTOK, DD, DFFN);

    // residual + LN2 -> output
    add_ln_kernel<<<MTOK, 128>>>(hb, ff2, ln2g, ln2b, (float*)d_out);
}